// round 2
// baseline (speedup 1.0000x reference)
#include <cuda_runtime.h>
#include <cuda_bf16.h>
#include <math.h>

#define BB 8
#define CC 64
#define NN 4096
#define HH 4
#define OO 128
#define KNN 20
#define PP (BB*NN)   // 32768

// ---------------- scratch (device globals; no allocs) ----------------
__device__ float g_pdist[(size_t)BB*NN*NN];   // 536 MB
__device__ float g_pts[(size_t)PP*CC];        // (B,N,C) transposed x
__device__ float g_sq[PP];
__device__ int   g_idx[PP*KNN];
__device__ float g_M[HH*CC*CC];               // Wq^T Wk per head
__device__ float g_Wf[OO*HH*CC];              // Wout folded with Wv
__device__ float g_wd[(size_t)PP*HH*CC];      // weighted difference vectors
__device__ float g_y[(size_t)BB*OO*NN];       // pre-BN output
__device__ float g_mean[OO];
__device__ float g_istd[OO];

// ---------------- K0: transpose x -> pts ----------------
__global__ void k_transpose(const float* __restrict__ x) {
    __shared__ float tile[32][33];
    int b = blockIdx.z;
    int n0 = blockIdx.x * 32, c0 = blockIdx.y * 32;
    for (int i = threadIdx.y; i < 32; i += 8)
        tile[i][threadIdx.x] = x[((size_t)b*CC + c0 + i)*NN + n0 + threadIdx.x];
    __syncthreads();
    for (int i = threadIdx.y; i < 32; i += 8)
        g_pts[((size_t)b*NN + n0 + i)*CC + c0 + threadIdx.x] = tile[threadIdx.x][i];
}

// ---------------- K0b: copy x into out channels [128,192) ----------------
__global__ void k_copyx(const float* __restrict__ x, float* __restrict__ out) {
    size_t i = (size_t)blockIdx.x * blockDim.x + threadIdx.x;
    if (i >= (size_t)BB*CC*NN) return;
    int n = (int)(i & (NN-1));
    size_t t = i >> 12;
    int c = (int)(t & (CC-1));
    int b = (int)(t >> 6);
    out[((size_t)b*192 + 128 + c)*NN + n] = x[i];
}

// ---------------- K1: squared norms ----------------
__global__ void k_sqnorm() {
    int p = blockIdx.x * 8 + (threadIdx.x >> 5);
    int lane = threadIdx.x & 31;
    float v0 = g_pts[(size_t)p*64 + lane];
    float v1 = g_pts[(size_t)p*64 + 32 + lane];
    float s = v0*v0 + v1*v1;
    #pragma unroll
    for (int off = 16; off; off >>= 1) s += __shfl_xor_sync(0xFFFFFFFFu, s, off);
    if (lane == 0) g_sq[p] = s;
}

// ---------------- K2: precompute M = Wq^T Wk per head ----------------
__global__ void k_precM(const float* __restrict__ Wq, const float* __restrict__ Wk) {
    int id = blockIdx.x * 256 + threadIdx.x;     // H*64*64 = 16384
    int cp = id & 63;
    int c  = (id >> 6) & 63;
    int h  = id >> 12;
    float acc = 0.f;
    #pragma unroll 8
    for (int e = 0; e < 64; e++)
        acc += Wq[(h*64 + e)*64 + c] * Wk[(h*64 + e)*64 + cp];
    g_M[id] = acc;
}

// ---------------- K2b: precompute Wf = Wout folded with Wv ----------------
__global__ void k_precWf(const float* __restrict__ Wout, const float* __restrict__ Wv) {
    int id = blockIdx.x * 256 + threadIdx.x;     // O*H*C = 32768
    int c = id & 63;
    int h = (id >> 6) & 3;
    int o = id >> 8;
    float acc = 0.f;
    #pragma unroll 8
    for (int v = 0; v < 64; v++)
        acc += Wout[o*256 + h*64 + v] * Wv[(h*64 + v)*64 + c];
    g_Wf[id] = acc;
}

// ---------------- K3: pairwise -dist^2 (Gram) ----------------
__global__ void k_pdist() {
    __shared__ float As[64][65];
    __shared__ float Bs[64][65];
    __shared__ float sqa[64], sqb[64];
    int b = blockIdx.z;
    int i0 = blockIdx.y * 64, j0 = blockIdx.x * 64;
    int tid = threadIdx.y * 16 + threadIdx.x;
    const float* pa = g_pts + ((size_t)b*NN + i0)*64;
    const float* pb = g_pts + ((size_t)b*NN + j0)*64;
    for (int t = tid; t < 4096; t += 256) {
        As[t >> 6][t & 63] = pa[t];
        Bs[t >> 6][t & 63] = pb[t];
    }
    if (tid < 64) sqa[tid] = g_sq[b*NN + i0 + tid];
    else if (tid < 128) sqb[tid - 64] = g_sq[b*NN + j0 + tid - 64];
    __syncthreads();

    float acc[4][4] = {};
    int ri = threadIdx.y * 4, rj = threadIdx.x * 4;
    #pragma unroll 4
    for (int k = 0; k < 64; k++) {
        float a0 = As[ri][k], a1 = As[ri+1][k], a2 = As[ri+2][k], a3 = As[ri+3][k];
        float b0 = Bs[rj][k], b1 = Bs[rj+1][k], b2 = Bs[rj+2][k], b3 = Bs[rj+3][k];
        acc[0][0] += a0*b0; acc[0][1] += a0*b1; acc[0][2] += a0*b2; acc[0][3] += a0*b3;
        acc[1][0] += a1*b0; acc[1][1] += a1*b1; acc[1][2] += a1*b2; acc[1][3] += a1*b3;
        acc[2][0] += a2*b0; acc[2][1] += a2*b1; acc[2][2] += a2*b2; acc[2][3] += a2*b3;
        acc[3][0] += a3*b0; acc[3][1] += a3*b1; acc[3][2] += a3*b2; acc[3][3] += a3*b3;
    }
    #pragma unroll
    for (int ii = 0; ii < 4; ii++) {
        size_t row = ((size_t)b*NN + i0 + ri + ii)*NN + j0 + rj;
        float si = sqa[ri + ii];
        #pragma unroll
        for (int jj = 0; jj < 4; jj++)
            g_pdist[row + jj] = 2.f*acc[ii][jj] - si - sqb[rj + jj];
    }
}

// ---------------- K4: top-21 per row, drop first ----------------
__global__ void k_topk() {
    __shared__ float dist[4096];
    __shared__ float smax[8];
    __shared__ int   simax[8];
    __shared__ int   s_besti;
    int tid = threadIdx.x;
    int lane = tid & 31, wid = tid >> 5;
    size_t row = (size_t)blockIdx.x * 4096;
    for (int t = tid; t < 4096; t += 256) dist[t] = g_pdist[row + t];
    __syncthreads();

    for (int sel = 0; sel < KNN + 1; sel++) {
        float v = -3.402823466e38f;
        int vi = 0x7FFFFFFF;
        for (int t = tid; t < 4096; t += 256) {
            float d = dist[t];
            if (d > v) { v = d; vi = t; }
        }
        #pragma unroll
        for (int off = 16; off; off >>= 1) {
            float ov = __shfl_xor_sync(0xFFFFFFFFu, v, off);
            int   oi = __shfl_xor_sync(0xFFFFFFFFu, vi, off);
            if (ov > v || (ov == v && oi < vi)) { v = ov; vi = oi; }
        }
        if (lane == 0) { smax[wid] = v; simax[wid] = vi; }
        __syncthreads();
        if (tid == 0) {
            float bv = smax[0]; int bi = simax[0];
            #pragma unroll
            for (int w = 1; w < 8; w++) {
                if (smax[w] > bv || (smax[w] == bv && simax[w] < bi)) { bv = smax[w]; bi = simax[w]; }
            }
            s_besti = bi;
            if (sel > 0) g_idx[blockIdx.x * KNN + sel - 1] = bi;
            dist[bi] = -3.402823466e38f;
        }
        __syncthreads();
    }
}

// ---------------- K5: per-point attention -> weighted difference vectors ----------------
#define WPB 8
__global__ void k_attn() {
    __shared__ float nb[WPB][KNN][64];
    __shared__ float qs[WPB][64];
    __shared__ float tq[WPB][64];
    __shared__ float ps[WPB][KNN];
    __shared__ int   nbi[WPB][KNN];

    int w = threadIdx.x >> 5;
    int lane = threadIdx.x & 31;
    int p = blockIdx.x * WPB + w;
    int b = p >> 12;

    if (lane < KNN) nbi[w][lane] = g_idx[p * KNN + lane];
    float q0 = g_pts[(size_t)p*64 + lane];
    float q1 = g_pts[(size_t)p*64 + 32 + lane];
    qs[w][lane] = q0;
    qs[w][lane + 32] = q1;
    __syncwarp();
    #pragma unroll 4
    for (int k = 0; k < KNN; k++) {
        int j = nbi[w][k];
        const float* src = g_pts + ((size_t)(b << 12) + j)*64;
        nb[w][k][lane]      = src[lane];
        nb[w][k][lane + 32] = src[lane + 32];
    }
    __syncwarp();

    for (int h = 0; h < HH; h++) {
        const float* Mh = g_M + h * 4096;
        float t0 = 0.f, t1 = 0.f;
        #pragma unroll 8
        for (int c = 0; c < 64; c++) {
            float qc = qs[w][c];
            t0 += qc * __ldg(Mh + c*64 + lane);
            t1 += qc * __ldg(Mh + c*64 + 32 + lane);
        }
        tq[w][lane] = t0;
        tq[w][lane + 32] = t1;
        __syncwarp();

        float s = -3.402823466e38f;
        if (lane < KNN) {
            float acc = 0.f;
            #pragma unroll 8
            for (int c = 0; c < 64; c++) acc += tq[w][c] * nb[w][lane][c];
            s = acc * 0.125f;   // / sqrt(64)
        }
        float mx = s;
        #pragma unroll
        for (int off = 16; off; off >>= 1) mx = fmaxf(mx, __shfl_xor_sync(0xFFFFFFFFu, mx, off));
        float e = (lane < KNN) ? expf(s - mx) : 0.f;
        float sum = e;
        #pragma unroll
        for (int off = 16; off; off >>= 1) sum += __shfl_xor_sync(0xFFFFFFFFu, sum, off);
        if (lane < KNN) ps[w][lane] = e / sum;
        __syncwarp();

        float w0 = 0.f, w1 = 0.f;
        #pragma unroll 4
        for (int k = 0; k < KNN; k++) {
            float pk = ps[w][k];
            w0 += pk * (nb[w][k][lane]      - q0);
            w1 += pk * (nb[w][k][lane + 32] - q1);
        }
        g_wd[((size_t)p*HH + h)*64 + lane]      = w0;
        g_wd[((size_t)p*HH + h)*64 + 32 + lane] = w1;
        __syncwarp();
    }
}

// ---------------- K6: y = Wf (128x256) @ wd^T ----------------
__global__ void k_ygemm() {
    __shared__ float Wfs[32][129];
    __shared__ float wds[64][33];
    int tid = threadIdx.y * 16 + threadIdx.x;
    int p0 = blockIdx.x * 64;
    float acc[8][4] = {};

    for (int kt = 0; kt < 8; kt++) {
        for (int t = tid; t < 4096; t += 256) {
            int o = t >> 5, k = t & 31;
            Wfs[k][o] = g_Wf[o*256 + kt*32 + k];
        }
        for (int t = tid; t < 2048; t += 256) {
            int pp = t >> 5, k = t & 31;
            wds[pp][k] = g_wd[(size_t)(p0 + pp)*256 + kt*32 + k];
        }
        __syncthreads();
        #pragma unroll 8
        for (int k = 0; k < 32; k++) {
            float a[8], bb[4];
            #pragma unroll
            for (int ii = 0; ii < 8; ii++) a[ii] = Wfs[k][threadIdx.y*8 + ii];
            #pragma unroll
            for (int jj = 0; jj < 4; jj++) bb[jj] = wds[threadIdx.x*4 + jj][k];
            #pragma unroll
            for (int ii = 0; ii < 8; ii++)
                #pragma unroll
                for (int jj = 0; jj < 4; jj++)
                    acc[ii][jj] += a[ii] * bb[jj];
        }
        __syncthreads();
    }
    #pragma unroll
    for (int ii = 0; ii < 8; ii++) {
        int o = threadIdx.y*8 + ii;
        #pragma unroll
        for (int jj = 0; jj < 4; jj++) {
            int p = p0 + threadIdx.x*4 + jj;
            g_y[((size_t)(p >> 12)*OO + o)*NN + (p & 4095)] = acc[ii][jj];
        }
    }
}

// ---------------- K7: BN stats (double accumulation) ----------------
__global__ void k_bnstats() {
    __shared__ double rs[256], rss[256];
    int o = blockIdx.x;
    int tid = threadIdx.x;
    double s = 0.0, ss = 0.0;
    for (int b = 0; b < BB; b++) {
        const float* row = g_y + ((size_t)b*OO + o)*NN;
        for (int t = tid; t < NN; t += 256) {
            double v = (double)row[t];
            s += v; ss += v*v;
        }
    }
    rs[tid] = s; rss[tid] = ss;
    __syncthreads();
    for (int st = 128; st; st >>= 1) {
        if (tid < st) { rs[tid] += rs[tid + st]; rss[tid] += rss[tid + st]; }
        __syncthreads();
    }
    if (tid == 0) {
        double n = (double)(BB*NN);
        double mean = rs[0] / n;
        double var = rss[0] / n - mean*mean;
        g_mean[o] = (float)mean;
        g_istd[o] = (float)(1.0 / sqrt(var + 1e-5));
    }
}

// ---------------- K8: BN apply + LeakyReLU -> out channels [0,128) ----------------
__global__ void k_bnapply(const float* __restrict__ gamma, const float* __restrict__ beta,
                          float* __restrict__ out) {
    size_t i = (size_t)blockIdx.x * blockDim.x + threadIdx.x;
    if (i >= (size_t)BB*OO*NN) return;
    int n = (int)(i & (NN-1));
    size_t t = i >> 12;
    int o = (int)(t & (OO-1));
    int b = (int)(t >> 7);
    float v = (g_y[i] - g_mean[o]) * g_istd[o] * gamma[o] + beta[o];
    v = (v >= 0.f) ? v : 0.2f * v;
    out[((size_t)b*192 + o)*NN + n] = v;
}

// ---------------- launch ----------------
extern "C" void kernel_launch(void* const* d_in, const int* in_sizes, int n_in,
                              void* d_out, int out_size) {
    const float* x     = (const float*)d_in[0];
    const float* Wq    = (const float*)d_in[1];
    const float* Wk    = (const float*)d_in[2];
    const float* Wv    = (const float*)d_in[3];
    const float* Wout  = (const float*)d_in[4];
    const float* gamma = (const float*)d_in[5];
    const float* beta  = (const float*)d_in[6];
    float* out = (float*)d_out;

    k_transpose<<<dim3(NN/32, CC/32, BB), dim3(32, 8)>>>(x);
    k_copyx<<<(BB*CC*NN)/256, 256>>>(x, out);
    k_sqnorm<<<PP/8, 256>>>();
    k_precM<<<64, 256>>>(Wq, Wk);
    k_precWf<<<128, 256>>>(Wout, Wv);
    k_pdist<<<dim3(NN/64, NN/64, BB), dim3(16, 16)>>>();
    k_topk<<<PP, 256>>>();
    k_attn<<<PP/WPB, 256>>>();
    k_ygemm<<<PP/64, dim3(16, 16)>>>();
    k_bnstats<<<OO, 256>>>();
    k_bnapply<<<(BB*OO*NN)/256, 256>>>(gamma, beta, out);
}